// round 11
// baseline (speedup 1.0000x reference)
#include <cuda_runtime.h>
#include <cuda_bf16.h>
#include <cuda_fp16.h>
#include <math.h>
#include <stdint.h>

#define RR 20
#define NB 4
#define HH 480
#define WWI 640
#define hh 120
#define ww 160
#define FC 32
#define DC 32
#define HWSZ (HH*WWI)
#define CH 4

// Scratch (static device globals; no allocations). 16B-aligned: accessed via uint4.
__device__ float g_rg [RR*NB*hh*ww];
__device__ unsigned g_idx[RR*NB*hh*ww];                          // packed pooled index (+bias)
__device__ __align__(16) __nv_bfloat16 g_featT[RR*NB*hh*ww*FC];  // [z][pos][ic]  98MB
__device__ __align__(16) __nv_bfloat16 g_adT [RR*NB*hh*ww*DC];   // [z][pos][ic]  98MB
__device__ __align__(16) __nv_bfloat16 g_dT  [NB*hh*ww*DC];      // [n][pos][oc]  bf16 d
__device__ __align__(16) __nv_bfloat16 g_wa_b[9*32*32];          // [tap][oc][ic]
__device__ __align__(16) __nv_bfloat16 g_wp_b[9*8*32];           // [tap][oc(8,pad)][ic]
__device__ float g_num[RR];
__device__ float g_den[RR];

// ---------------- PTX helpers ----------------
#define LDSM_X4(r0,r1,r2,r3,addr) \
    asm volatile("ldmatrix.sync.aligned.m8n8.x4.shared.b16 {%0,%1,%2,%3}, [%4];" \
        : "=r"(r0),"=r"(r1),"=r"(r2),"=r"(r3) : "r"(addr))

#define LDSM_X2(r0,r1,addr) \
    asm volatile("ldmatrix.sync.aligned.m8n8.x2.shared.b16 {%0,%1}, [%2];" \
        : "=r"(r0),"=r"(r1) : "r"(addr))

#define MMA_BF16(d, a0,a1,a2,a3, b0,b1) \
    asm volatile("mma.sync.aligned.m16n8k16.row.col.f32.bf16.bf16.f32 " \
        "{%0,%1,%2,%3},{%4,%5,%6,%7},{%8,%9},{%0,%1,%2,%3};" \
        : "+f"((d)[0]),"+f"((d)[1]),"+f"((d)[2]),"+f"((d)[3]) \
        : "r"(a0),"r"(a1),"r"(a2),"r"(a3),"r"(b0),"r"(b1))

__global__ void k_zero() {
    int t = threadIdx.x;
    if (t < RR) { g_num[t] = 0.f; g_den[t] = 0.f; }
}

// ---------------- weight convert ----------------
__global__ void k_wcvt(const float* __restrict__ Wa, const float* __restrict__ Wp) {
    int t = blockIdx.x * 256 + threadIdx.x;
    if (t < 9*32*32) {
        int ic = t & 31, oc = (t >> 5) & 31, tap = t >> 10;
        g_wa_b[t] = __float2bfloat16(Wa[(oc*32 + ic)*9 + tap]);
    }
    if (t < 9*8*32) {
        int ic = t & 31, oc = (t >> 5) & 7, tap = t >> 8;
        float v = (oc < 4) ? Wp[(oc*32 + ic)*9 + tap] : 0.f;
        g_wp_b[t] = __float2bfloat16(v);
    }
}

// ---------------- d transpose/convert: [n][oc][pos] f32 -> [n][pos][oc] bf16 -----
__global__ void k_dcvt(const float* __restrict__ dd) {
    __shared__ float s[32][65];
    int p0 = blockIdx.x * 64, n = blockIdx.y;
    int tid = threadIdx.x;
    for (int t = tid; t < 2048; t += 256) {
        int oc = t >> 6, p = t & 63;
        s[oc][p] = dd[(n*32 + oc)*19200 + p0 + p];
    }
    __syncthreads();
    for (int t = tid; t < 2048; t += 256) {
        int p = t >> 5, oc = t & 31;
        g_dT[(n*19200 + p0 + p)*32 + oc] = __float2bfloat16(s[oc][p]);
    }
}

// ---------------- Kernel 1: random pooling (tiled gts) -> g_rg, g_idx ----------
// block (32,4)=128; pooled tile 4x32; grid (5, 30, NB). gts tile staged once,
// rand streamed per r.
__global__ void __launch_bounds__(128) k_pool(const float* __restrict__ gts,
                                              const float* __restrict__ rnd) {
    __shared__ float s_g[16*128];
    int tx = threadIdx.x, ty = threadIdx.y;
    int tid = ty*32 + tx;
    int j0 = blockIdx.x*32, i0 = blockIdx.y*4, n = blockIdx.z;

    const float* gp = gts + n*HWSZ;
    for (int t = tid; t < 512; t += 128) {
        int row = t >> 5, c4 = t & 31;
        float4 v = *reinterpret_cast<const float4*>(
            gp + (4*i0 + row)*WWI + 4*j0 + c4*4);
        *reinterpret_cast<float4*>(&s_g[row*128 + c4*4]) = v;
    }
    __syncthreads();

    int i = i0 + ty, j = j0 + tx;
    float ga[4][4];
    #pragma unroll
    for (int bi = 0; bi < 4; bi++)
        #pragma unroll
        for (int bj = 0; bj < 4; bj++)
            ga[bi][bj] = s_g[(ty*4 + bi)*128 + tx*4 + bj];

    for (int r = 0; r < RR; r++) {
        const float* rp = rnd + (r*NB + n)*HWSZ + (4*i)*WWI + 4*j;
        float best = -1.f; int bloc = 0; float bg = 0.f;
        #pragma unroll
        for (int bi = 0; bi < 4; bi++) {
            float4 r4 = *reinterpret_cast<const float4*>(rp + bi*WWI);
            float ra[4] = {r4.x, r4.y, r4.z, r4.w};
            #pragma unroll
            for (int bj = 0; bj < 4; bj++) {
                float rm = (ga[bi][bj] > 0.1f) ? ra[bj] : 0.f;
                if (rm > best) { best = rm; bloc = bi*4 + bj; bg = ga[bi][bj]; }
            }
        }
        int bi = bloc >> 2, bj = bloc & 3;
        int row = 4*i + bi, col = 4*j + bj;
        int idx = ((r*NB + n)*hh + i)*ww + j;
        g_rg[idx] = (bg < 0.1f) ? 0.f : bg;
        g_idx[idx] = (unsigned)(row*WWI + col + 1282);
    }
}

// ---------------- Kernel 2: grid sample -> bf16 featT [z][pos][ic] ----------------
// block (32,4)=128; tile 4x32 positions, 4 ic per block; grid (5, 30, 32).
__global__ void __launch_bounds__(128) k_sample(const float* __restrict__ x) {
    __shared__ __align__(16) __nv_bfloat16 s_xi[2640*CH];   // [pos(20x132)][ic4] 21120B
    int tx = threadIdx.x, ty = threadIdx.y;
    int tid = ty*32 + tx;
    int j0 = blockIdx.x * 32, i0 = blockIdx.y * 4;
    int zb = blockIdx.z; int n = zb & 3, icg = zb >> 2;   // icg 0..7
    int i = i0 + ty, j = j0 + tx;
    int rb = 4*i0, cb = 4*j0;

    // phase A: fetch packed pooled indices
    unsigned lc[RR];
    #pragma unroll
    for (int r = 0; r < RR; r++)
        lc[r] = g_idx[((r*NB + n)*hh + i)*ww + j];

    // phase B: stage 4 channels interleaved
    const float* xbase = x + (n*FC + icg*CH) * HWSZ;
    for (int t = tid; t < 2640; t += 128) {
        int lr = t / 132, lcx = t - lr*132;
        int gy = min(rb + lr, HH-1), gx2 = min(cb + lcx, WWI-1);
        const float* p = xbase + gy*WWI + gx2;
        __nv_bfloat162 pk0, pk1;
        pk0.x = __float2bfloat16(p[0]);
        pk0.y = __float2bfloat16(p[HWSZ]);
        pk1.x = __float2bfloat16(p[2*HWSZ]);
        pk1.y = __float2bfloat16(p[3*HWSZ]);
        *reinterpret_cast<__nv_bfloat162*>(&s_xi[t*CH])     = pk0;
        *reinterpret_cast<__nv_bfloat162*>(&s_xi[t*CH + 2]) = pk1;
    }
    __syncthreads();

    // phase C: 20 samples, vectorized over 4 ic
    const uint2* sp = reinterpret_cast<const uint2*>(s_xi);
    unsigned fbmask = 0;
    #pragma unroll
    for (int r = 0; r < RR; r++) {
        unsigned idx2 = lc[r];
        int row2 = (int)(idx2 / 640u);
        int col2 = (int)(idx2 - (unsigned)row2*640u);
        float gxn = 2.f*((float)col2/640.f - 0.5f);
        float gyn = 2.f*((float)row2/480.f - 0.5f);
        float ixv = (gxn + 1.f)*0.5f*639.f;
        float iyv = (gyn + 1.f)*0.5f*479.f;
        float x0f = floorf(ixv), y0f = floorf(iyv);
        int x0 = (int)x0f, y0 = (int)y0f;
        float wx = ixv - x0f, wy = iyv - y0f;
        if (!(x0 >= cb && x0+1 <= cb+131 && y0 >= rb && y0+1 <= rb+19)) {
            fbmask |= 1u << r; continue;
        }
        float m0 = (y0 <= HH-1) ? 1.f : 0.f;
        float m1 = (y0+1 <= HH-1) ? 1.f : 0.f;
        float wy0 = (1.f - wy) * m0, wy1 = wy * m1;
        __nv_bfloat162 W00 = __float2bfloat162_rn((1.f - wx) * wy0);
        __nv_bfloat162 W10 = __float2bfloat162_rn(wx * wy0);
        __nv_bfloat162 W01 = __float2bfloat162_rn((1.f - wx) * wy1);
        __nv_bfloat162 W11 = __float2bfloat162_rn(wx * wy1);
        unsigned off = (unsigned)((y0 - rb)*132 + (x0 - cb));
        uint2 q00 = sp[off], q10 = sp[off+1], q01 = sp[off+132], q11 = sp[off+133];
        const __nv_bfloat162* a00 = reinterpret_cast<const __nv_bfloat162*>(&q00);
        const __nv_bfloat162* a10 = reinterpret_cast<const __nv_bfloat162*>(&q10);
        const __nv_bfloat162* a01 = reinterpret_cast<const __nv_bfloat162*>(&q01);
        const __nv_bfloat162* a11 = reinterpret_cast<const __nv_bfloat162*>(&q11);
        uint2 outv;
        __nv_bfloat162* o = reinterpret_cast<__nv_bfloat162*>(&outv);
        #pragma unroll
        for (int p2 = 0; p2 < 2; p2++)
            o[p2] = __hfma2(a00[p2], W00,
                     __hfma2(a10[p2], W10,
                      __hfma2(a01[p2], W01, __hmul2(a11[p2], W11))));
        int z = r*NB + n;
        *reinterpret_cast<uint2*>(
            &g_featT[(z*19200 + i*160 + j)*32 + icg*CH]) = outv;
    }

    // rare fallback (column-wrap): full recompute from global, f32
    while (fbmask) {
        int r = __ffs(fbmask) - 1;
        fbmask &= fbmask - 1;
        unsigned idx2 = lc[r];
        int row2 = (int)(idx2 / 640u);
        int col2 = (int)(idx2 - (unsigned)row2*640u);
        float gxn = 2.f*((float)col2/640.f - 0.5f);
        float gyn = 2.f*((float)row2/480.f - 0.5f);
        float ixv = (gxn + 1.f)*0.5f*639.f;
        float iyv = (gyn + 1.f)*0.5f*479.f;
        float x0f = floorf(ixv), y0f = floorf(iyv);
        float fwx = ixv - x0f, fwy = iyv - y0f;
        int X0 = (int)x0f, Y0 = (int)y0f;
        int xa = min(max(X0,   0), WWI-1), xb = min(max(X0+1, 0), WWI-1);
        int ya = min(max(Y0,   0), HH-1),  yb = min(max(Y0+1, 0), HH-1);
        bool okx0 = (X0 >= 0) && (X0 <= WWI-1);
        bool okx1 = (X0+1 <= WWI-1);
        bool oky0 = (Y0 >= 0) && (Y0 <= HH-1);
        bool oky1 = (Y0+1 <= HH-1);
        float w00 = (okx0 && oky0) ? (1.f-fwx)*(1.f-fwy) : 0.f;
        float w10 = (okx1 && oky0) ? fwx*(1.f-fwy) : 0.f;
        float w01 = (okx0 && oky1) ? (1.f-fwx)*fwy : 0.f;
        float w11 = (okx1 && oky1) ? fwx*fwy : 0.f;
        uint2 outv;
        __nv_bfloat16* o = reinterpret_cast<__nv_bfloat16*>(&outv);
        #pragma unroll
        for (int c = 0; c < CH; c++) {
            const float* xp = xbase + c*HWSZ;
            float v = xp[ya*WWI+xa]*w00 + xp[ya*WWI+xb]*w10
                    + xp[yb*WWI+xa]*w01 + xp[yb*WWI+xb]*w11;
            o[c] = __float2bfloat16(v);
        }
        int z = r*NB + n;
        *reinterpret_cast<uint2*>(
            &g_featT[(z*19200 + i*160 + j)*32 + icg*CH]) = outv;
    }
}

// ---------------- Kernel 3: conv1 via mma.sync (bf16) + sigmoid*d -> g_adT --------
// block 256 = 8 warps; tile 8 rows x 32 cols; warp w owns row w (two m16 groups).
__global__ void __launch_bounds__(256) k_conv1(const float* __restrict__ ba) {
    __shared__ __align__(16) __nv_bfloat16 s_f[10*34*40];   // [row][col][ic pad40]
    __shared__ __align__(16) __nv_bfloat16 s_w[9*32*32];    // [tap][oc][ic]
    int tid = threadIdx.x, lane = tid & 31, wid = tid >> 5;
    int j0 = blockIdx.x*32, i0 = blockIdx.y*8, z = blockIdx.z;
    int n = z & 3;

    // stage weights (16B chunks): 9*32*32 bf16 = 18432B = 1152 uint4
    {
        const uint4* src = (const uint4*)g_wa_b;
        uint4* dst = (uint4*)s_w;
        for (int t = tid; t < 1152; t += 256) dst[t] = src[t];
    }
    // stage feat from g_featT[z][pos][ic] (uint4 chunks, no transpose)
    for (int t = tid; t < 10*34*4; t += 256) {
        int chunk = t & 3; int lj = (t >> 2) % 34; int li = t / 136;
        int gi = i0 - 1 + li, gj = j0 - 1 + lj;
        uint4 v = make_uint4(0,0,0,0);
        if (gi >= 0 && gi < hh && gj >= 0 && gj < ww)
            v = *reinterpret_cast<const uint4*>(
                &g_featT[(z*19200 + gi*160 + gj)*32 + chunk*8]);
        *reinterpret_cast<uint4*>(&s_f[(li*34 + lj)*40 + chunk*8]) = v;
    }
    __syncthreads();

    uint32_t sfb = (uint32_t)__cvta_generic_to_shared(s_f);
    uint32_t swb = (uint32_t)__cvta_generic_to_shared(s_w);
    int r = wid;
    int m = lane & 15;
    int koff = (lane >> 4) * 8;
    uint32_t baseA0 = sfb + (uint32_t)((((r+1)*34 + (m + 1))*40 + koff) * 2);
    int lg = lane >> 3, lr = lane & 7;
    int nrow_off = ((lg & 2) ? 8 : 0) + lr;
    int kboff = (lg & 1) ? 8 : 0;

    float acc[2][4][4];
    #pragma unroll
    for (int s = 0; s < 2; s++)
        #pragma unroll
        for (int nt = 0; nt < 4; nt++)
            #pragma unroll
            for (int q = 0; q < 4; q++) acc[s][nt][q] = 0.f;

    #pragma unroll
    for (int tap = 0; tap < 9; tap++) {
        int dy = tap/3 - 1, dx = tap%3 - 1;
        int offA = (dy*34 + dx)*40*2;
        #pragma unroll
        for (int kc = 0; kc < 2; kc++) {
            uint32_t a0[4], a1[4];
            uint32_t aad = baseA0 + offA + kc*32;
            LDSM_X4(a0[0],a0[1],a0[2],a0[3], aad);
            LDSM_X4(a1[0],a1[1],a1[2],a1[3], aad + 16*40*2);
            #pragma unroll
            for (int p = 0; p < 2; p++) {
                uint32_t bad = swb + (uint32_t)((((tap*32 + p*16 + nrow_off))*32 + kc*16 + kboff) * 2);
                uint32_t b0,b1,b2,b3;
                LDSM_X4(b0,b1,b2,b3, bad);
                MMA_BF16(acc[0][2*p  ], a0[0],a0[1],a0[2],a0[3], b0,b1);
                MMA_BF16(acc[0][2*p+1], a0[0],a0[1],a0[2],a0[3], b2,b3);
                MMA_BF16(acc[1][2*p  ], a1[0],a1[1],a1[2],a1[3], b0,b1);
                MMA_BF16(acc[1][2*p+1], a1[0],a1[1],a1[2],a1[3], b2,b3);
            }
        }
    }

    // epilogue: bias + sigmoid, * d (bf16 transposed), store bf16 [pos][oc]
    int i = i0 + r;
    #pragma unroll
    for (int s = 0; s < 2; s++) {
        int cbase = s*16 + (lane >> 2);
        #pragma unroll
        for (int nt = 0; nt < 4; nt++) {
            int oc = nt*8 + 2*(lane & 3);
            float b0v = ba[oc], b1v = ba[oc+1];
            #pragma unroll
            for (int half = 0; half < 2; half++) {
                int c = cbase + half*8;
                int j = j0 + c;
                float v0 = acc[s][nt][half*2+0] + b0v;
                float v1 = acc[s][nt][half*2+1] + b1v;
                float att0 = 1.f/(1.f + __expf(-v0));
                float att1 = 1.f/(1.f + __expf(-v1));
                __nv_bfloat162 dv = *reinterpret_cast<const __nv_bfloat162*>(
                    &g_dT[(n*19200 + i*160 + j)*32 + oc]);
                __nv_bfloat162 pk;
                pk.x = __float2bfloat16(att0 * __bfloat162float(dv.x));
                pk.y = __float2bfloat16(att1 * __bfloat162float(dv.y));
                *reinterpret_cast<__nv_bfloat162*>(
                    &g_adT[(z*19200 + i*160 + j)*32 + oc]) = pk;
            }
        }
    }
}

// ---------------- Kernel 4: conv2 via mma.sync + fused loss ----------------
__global__ void __launch_bounds__(256) k_conv2(const float* __restrict__ bp) {
    __shared__ __align__(16) __nv_bfloat16 s_a[10*34*40];
    __shared__ __align__(16) __nv_bfloat16 s_w2[9*8*32];
    __shared__ float s_rg[10*36];
    __shared__ float s_red[16];
    int tid = threadIdx.x, lane = tid & 31, wid = tid >> 5;
    int j0 = blockIdx.x*32, i0 = blockIdx.y*8, z = blockIdx.z;
    int rr = z >> 2;

    // stage weights: 9*8*32 bf16 = 4608B = 288 uint4
    {
        const uint4* src = (const uint4*)g_wp_b;
        uint4* dst = (uint4*)s_w2;
        for (int t = tid; t < 288; t += 256) dst[t] = src[t];
    }
    for (int t = tid; t < 10*34; t += 256) {
        int lcx = t % 34, lrr = t / 34;
        int gi = i0 - 1 + lrr, gj = j0 - 1 + lcx;
        float v = 0.f;
        if (gi >= 0 && gi < hh && gj >= 0 && gj < ww) v = g_rg[(z*hh + gi)*ww + gj];
        s_rg[lrr*36 + lcx] = v;
    }
    // stage ad: g_adT[z][pos][ic] -> s_a[li][lj][ic]  (16B chunks)
    for (int t = tid; t < 10*34*4; t += 256) {
        int chunk = t & 3; int lj = (t >> 2) % 34; int li = t / 136;
        int gi = i0 - 1 + li, gj = j0 - 1 + lj;
        uint4 v = make_uint4(0,0,0,0);
        if (gi >= 0 && gi < hh && gj >= 0 && gj < ww)
            v = *reinterpret_cast<const uint4*>(
                &g_adT[(z*19200 + gi*160 + gj)*32 + chunk*8]);
        *reinterpret_cast<uint4*>(&s_a[(li*34 + lj)*40 + chunk*8]) = v;
    }
    __syncthreads();

    uint32_t sab = (uint32_t)__cvta_generic_to_shared(s_a);
    uint32_t swb = (uint32_t)__cvta_generic_to_shared(s_w2);
    int r = wid;
    int m = lane & 15;
    int koff = (lane >> 4) * 8;
    uint32_t baseA0 = sab + (uint32_t)((((r+1)*34 + (m + 1))*40 + koff) * 2);
    int nrow2 = lane & 7;
    int kboff2 = ((lane >> 3) & 1) ? 8 : 0;

    float acc[2][4];
    #pragma unroll
    for (int s = 0; s < 2; s++)
        #pragma unroll
        for (int q = 0; q < 4; q++) acc[s][q] = 0.f;

    #pragma unroll
    for (int tap = 0; tap < 9; tap++) {
        int dy = tap/3 - 1, dx = tap%3 - 1;
        int offA = (dy*34 + dx)*40*2;
        #pragma unroll
        for (int kc = 0; kc < 2; kc++) {
            uint32_t a0[4], a1[4];
            uint32_t aad = baseA0 + offA + kc*32;
            LDSM_X4(a0[0],a0[1],a0[2],a0[3], aad);
            LDSM_X4(a1[0],a1[1],a1[2],a1[3], aad + 16*40*2);
            uint32_t bad = swb + (uint32_t)(((tap*8 + nrow2)*32 + kc*16 + kboff2) * 2);
            uint32_t b0,b1;
            LDSM_X2(b0,b1, bad);
            MMA_BF16(acc[0], a0[0],a0[1],a0[2],a0[3], b0,b1);
            MMA_BF16(acc[1], a1[0],a1[1],a1[2],a1[3], b0,b1);
        }
    }

    // loss epilogue
    float num = 0.f, den = 0.f;
    int ocl = 2*(lane & 3);
    if (ocl < 4) {
        #pragma unroll
        for (int s = 0; s < 2; s++) {
            #pragma unroll
            for (int q = 0; q < 4; q++) {
                int oc = ocl + (q & 1);
                int m2 = (lane >> 2) + ((q >> 1) * 8);
                int c = s*16 + m2;
                float ds = acc[s][q] + bp[oc];
                int ox = (oc >= 1) ? 1 : 0;
                int oy = (oc < 2) ? 1 : ((oc == 2) ? 0 : -1);
                float cen = s_rg[(r+1)*36 + (c+1)];
                float nbv = s_rg[(r+1+ox)*36 + (c+1+oy)];
                float grad = __logf(cen + 1e-6f) - __logf(nbv + 1e-6f);
                float a = fabsf(ds - grad);
                float sl1 = (a < 0.01f) ? (0.5f*a*a/0.01f) : (a - 0.005f);
                if (cen > 0.1f && nbv > 0.1f) { num += sl1; den += 1.f; }
            }
        }
    }
    #pragma unroll
    for (int o = 16; o > 0; o >>= 1) {
        num += __shfl_down_sync(0xffffffffu, num, o);
        den += __shfl_down_sync(0xffffffffu, den, o);
    }
    if (lane == 0) { s_red[wid] = num; s_red[8 + wid] = den; }
    __syncthreads();
    if (tid == 0) {
        float sn = 0.f, sd = 0.f;
        #pragma unroll
        for (int w = 0; w < 8; w++) { sn += s_red[w]; sd += s_red[8+w]; }
        atomicAdd(&g_num[rr], sn);
        atomicAdd(&g_den[rr], sd);
    }
}

__global__ void k_final(float* out) {
    if (threadIdx.x == 0) {
        float tot = 0.f;
        for (int r = 0; r < RR; r++) tot += g_num[r] / g_den[r];
        out[0] = tot / 20.0f;
    }
}

extern "C" void kernel_launch(void* const* d_in, const int* in_sizes, int n_in,
                              void* d_out, int out_size) {
    const float* x    = (const float*)d_in[0];
    const float* d    = (const float*)d_in[1];
    const float* gts  = (const float*)d_in[2];
    const float* rnd  = (const float*)d_in[3];
    const float* Wa   = (const float*)d_in[4];
    const float* ba   = (const float*)d_in[5];
    const float* Wp   = (const float*)d_in[6];
    const float* bp   = (const float*)d_in[7];
    float* out = (float*)d_out;

    k_zero<<<1, 32>>>();
    k_wcvt<<<36, 256>>>(Wa, Wp);
    k_dcvt<<<dim3(300, 4), 256>>>(d);

    dim3 bs1(32, 4), gs1(ww/32, hh/4, NB);
    k_pool<<<gs1, bs1>>>(gts, rnd);

    dim3 bs2(32, 4), gs2(ww/32, hh/4, NB*8);
    k_sample<<<gs2, bs2>>>(x);

    dim3 bs3(256), gs3(ww/32, hh/8, RR*NB);
    k_conv1<<<gs3, bs3>>>(ba);

    dim3 bs4(256), gs4(ww/32, hh/8, RR*NB);
    k_conv2<<<gs4, bs4>>>(bp);

    k_final<<<1, 32>>>(out);
}

// round 12
// speedup vs baseline: 1.1181x; 1.1181x over previous
#include <cuda_runtime.h>
#include <cuda_bf16.h>
#include <cuda_fp16.h>
#include <math.h>
#include <stdint.h>

#define RR 20
#define NB 4
#define HH 480
#define WWI 640
#define hh 120
#define ww 160
#define FC 32
#define DC 32
#define HWSZ (HH*WWI)

// Scratch (static device globals; no allocations). 16B-aligned: accessed via uint4.
__device__ float g_rg [RR*NB*hh*ww];
__device__ unsigned g_idx[RR*NB*hh*ww];                          // packed pooled index (+bias)
__device__ __align__(16) __nv_bfloat16 g_featT[RR*NB*hh*ww*FC];  // [z][pos][ic]  98MB
__device__ __align__(16) __nv_bfloat16 g_adT [RR*NB*hh*ww*DC];   // [z][pos][ic]  98MB
__device__ __align__(16) __nv_bfloat16 g_dT  [NB*hh*ww*DC];      // [n][pos][oc]  bf16 d
__device__ __align__(16) __nv_bfloat16 g_wa_b[9*32*32];          // [tap][oc][ic]
__device__ __align__(16) __nv_bfloat16 g_wp_b[9*8*32];           // [tap][oc(8,pad)][ic]
__device__ float g_num[RR];
__device__ float g_den[RR];

// ---------------- PTX helpers ----------------
#define LDSM_X4(r0,r1,r2,r3,addr) \
    asm volatile("ldmatrix.sync.aligned.m8n8.x4.shared.b16 {%0,%1,%2,%3}, [%4];" \
        : "=r"(r0),"=r"(r1),"=r"(r2),"=r"(r3) : "r"(addr))

#define LDSM_X2(r0,r1,addr) \
    asm volatile("ldmatrix.sync.aligned.m8n8.x2.shared.b16 {%0,%1}, [%2];" \
        : "=r"(r0),"=r"(r1) : "r"(addr))

#define MMA_BF16(d, a0,a1,a2,a3, b0,b1) \
    asm volatile("mma.sync.aligned.m16n8k16.row.col.f32.bf16.bf16.f32 " \
        "{%0,%1,%2,%3},{%4,%5,%6,%7},{%8,%9},{%0,%1,%2,%3};" \
        : "+f"((d)[0]),"+f"((d)[1]),"+f"((d)[2]),"+f"((d)[3]) \
        : "r"(a0),"r"(a1),"r"(a2),"r"(a3),"r"(b0),"r"(b1))

__global__ void k_zero() {
    int t = threadIdx.x;
    if (t < RR) { g_num[t] = 0.f; g_den[t] = 0.f; }
}

// ---------------- weight convert ----------------
__global__ void k_wcvt(const float* __restrict__ Wa, const float* __restrict__ Wp) {
    int t = blockIdx.x * 256 + threadIdx.x;
    if (t < 9*32*32) {
        int ic = t & 31, oc = (t >> 5) & 31, tap = t >> 10;
        g_wa_b[t] = __float2bfloat16(Wa[(oc*32 + ic)*9 + tap]);
    }
    if (t < 9*8*32) {
        int ic = t & 31, oc = (t >> 5) & 7, tap = t >> 8;
        float v = (oc < 4) ? Wp[(oc*32 + ic)*9 + tap] : 0.f;
        g_wp_b[t] = __float2bfloat16(v);
    }
}

// ---------------- d transpose/convert: [n][oc][pos] f32 -> [n][pos][oc] bf16 -----
__global__ void k_dcvt(const float* __restrict__ dd) {
    __shared__ float s[32][65];
    int p0 = blockIdx.x * 64, n = blockIdx.y;
    int tid = threadIdx.x;
    for (int t = tid; t < 2048; t += 256) {
        int oc = t >> 6, p = t & 63;
        s[oc][p] = dd[(n*32 + oc)*19200 + p0 + p];
    }
    __syncthreads();
    for (int t = tid; t < 2048; t += 256) {
        int p = t >> 5, oc = t & 31;
        g_dT[(n*19200 + p0 + p)*32 + oc] = __float2bfloat16(s[oc][p]);
    }
}

// ---------------- Kernel 1: random pooling (tiled gts) -> g_rg, g_idx ----------
__global__ void __launch_bounds__(128) k_pool(const float* __restrict__ gts,
                                              const float* __restrict__ rnd) {
    __shared__ float s_g[16*128];
    int tx = threadIdx.x, ty = threadIdx.y;
    int tid = ty*32 + tx;
    int j0 = blockIdx.x*32, i0 = blockIdx.y*4, n = blockIdx.z;

    const float* gp = gts + n*HWSZ;
    for (int t = tid; t < 512; t += 128) {
        int row = t >> 5, c4 = t & 31;
        float4 v = *reinterpret_cast<const float4*>(
            gp + (4*i0 + row)*WWI + 4*j0 + c4*4);
        *reinterpret_cast<float4*>(&s_g[row*128 + c4*4]) = v;
    }
    __syncthreads();

    int i = i0 + ty, j = j0 + tx;
    float ga[4][4];
    #pragma unroll
    for (int bi = 0; bi < 4; bi++)
        #pragma unroll
        for (int bj = 0; bj < 4; bj++)
            ga[bi][bj] = s_g[(ty*4 + bi)*128 + tx*4 + bj];

    for (int r = 0; r < RR; r++) {
        const float* rp = rnd + (r*NB + n)*HWSZ + (4*i)*WWI + 4*j;
        float best = -1.f; int bloc = 0; float bg = 0.f;
        #pragma unroll
        for (int bi = 0; bi < 4; bi++) {
            float4 r4 = *reinterpret_cast<const float4*>(rp + bi*WWI);
            float ra[4] = {r4.x, r4.y, r4.z, r4.w};
            #pragma unroll
            for (int bj = 0; bj < 4; bj++) {
                float rm = (ga[bi][bj] > 0.1f) ? ra[bj] : 0.f;
                if (rm > best) { best = rm; bloc = bi*4 + bj; bg = ga[bi][bj]; }
            }
        }
        int bi = bloc >> 2, bj = bloc & 3;
        int row = 4*i + bi, col = 4*j + bj;
        int idx = ((r*NB + n)*hh + i)*ww + j;
        g_rg[idx] = (bg < 0.1f) ? 0.f : bg;
        g_idx[idx] = (unsigned)(row*WWI + col + 1282);
    }
}

// ---------------- Kernel 2: grid sample -> bf16 featT [z][pos][ic] ----------------
// R7 structure: block (32,4)=128; 8 ic per block; grid (5, 30, 16).
// Phase A decodes g_idx ONCE per r into packed {off,masks,fp16 wx,wy} registers;
// phase C: 4x LDS.128 corners + hfma2 + STG.128.
__global__ void __launch_bounds__(128) k_sample(const float* __restrict__ x) {
    __shared__ __align__(16) __nv_bfloat16 s_xi[2640*8];   // [pos(20x132)][ic8] 42240B
    int tx = threadIdx.x, ty = threadIdx.y;
    int tid = ty*32 + tx;
    int j0 = blockIdx.x * 32, i0 = blockIdx.y * 4;
    int zb = blockIdx.z; int n = zb & 3, icg = zb >> 2;    // icg 0..3
    int i = i0 + ty, j = j0 + tx;
    int rb = 4*i0, cb = 4*j0;

    // phase A: decode packed pooled index -> register-packed coords (once per r)
    uint2 lc[RR];
    #pragma unroll
    for (int r = 0; r < RR; r++) {
        unsigned idx2 = g_idx[((r*NB + n)*hh + i)*ww + j];
        int row2 = (int)(idx2 / 640u);
        int col2 = (int)(idx2 - (unsigned)row2*640u);
        float ixv = (float)col2 * (639.f/640.f);
        float iyv = (float)row2 * (479.f/480.f);
        float x0f = floorf(ixv), y0f = floorf(iyv);
        int x0 = (int)x0f, y0 = (int)y0f;
        float wx = ixv - x0f, wy = iyv - y0f;
        unsigned m0 = (y0 <= HH-1) ? 1u : 0u;
        unsigned m1 = (y0+1 <= HH-1) ? 1u : 0u;
        unsigned off;
        if (x0 >= cb && x0+1 <= cb+131 && y0 >= rb && y0+1 <= rb+19)
            off = (unsigned)((y0-rb)*132 + (x0-cb));
        else off = 0x3FFFu;
        unsigned w0 = off | (m0 << 14) | (m1 << 15)
                    | ((unsigned)__half_as_ushort(__float2half_rn(wx)) << 16);
        unsigned w1 = (unsigned)__half_as_ushort(__float2half_rn(wy));
        lc[r] = make_uint2(w0, w1);
    }

    // phase B: stage 8 channels interleaved
    const float* xbase = x + (n*FC + icg*8) * HWSZ;
    for (int t = tid; t < 2640; t += 128) {
        int lr = t / 132, lcx = t - lr*132;
        int gy = min(rb + lr, HH-1), gx2 = min(cb + lcx, WWI-1);
        const float* p = xbase + gy*WWI + gx2;
        #pragma unroll
        for (int c = 0; c < 8; c += 2) {
            __nv_bfloat162 pk;
            pk.x = __float2bfloat16(p[c*HWSZ]);
            pk.y = __float2bfloat16(p[(c+1)*HWSZ]);
            *reinterpret_cast<__nv_bfloat162*>(&s_xi[t*8 + c]) = pk;
        }
    }
    __syncthreads();

    // phase C: 20 samples, vectorized over 8 ic
    const uint4* sp = reinterpret_cast<const uint4*>(s_xi);
    unsigned fbmask = 0;
    #pragma unroll
    for (int r = 0; r < RR; r++) {
        unsigned w0 = lc[r].x, w1 = lc[r].y;
        unsigned off = w0 & 0x3FFFu;
        if (off == 0x3FFFu) { fbmask |= (1u << r); continue; }
        float wx = __half2float(__ushort_as_half((unsigned short)(w0 >> 16)));
        float wy = __half2float(__ushort_as_half((unsigned short)(w1 & 0xFFFFu)));
        float m0 = (w0 & (1u<<14)) ? 1.f : 0.f;
        float m1 = (w0 & (1u<<15)) ? 1.f : 0.f;
        float wy0 = (1.f - wy) * m0, wy1 = wy * m1;
        __nv_bfloat162 W00 = __float2bfloat162_rn((1.f - wx) * wy0);
        __nv_bfloat162 W10 = __float2bfloat162_rn(wx * wy0);
        __nv_bfloat162 W01 = __float2bfloat162_rn((1.f - wx) * wy1);
        __nv_bfloat162 W11 = __float2bfloat162_rn(wx * wy1);
        uint4 q00 = sp[off], q10 = sp[off+1], q01 = sp[off+132], q11 = sp[off+133];
        const __nv_bfloat162* a00 = reinterpret_cast<const __nv_bfloat162*>(&q00);
        const __nv_bfloat162* a10 = reinterpret_cast<const __nv_bfloat162*>(&q10);
        const __nv_bfloat162* a01 = reinterpret_cast<const __nv_bfloat162*>(&q01);
        const __nv_bfloat162* a11 = reinterpret_cast<const __nv_bfloat162*>(&q11);
        uint4 outv;
        __nv_bfloat162* o = reinterpret_cast<__nv_bfloat162*>(&outv);
        #pragma unroll
        for (int p4 = 0; p4 < 4; p4++)
            o[p4] = __hfma2(a00[p4], W00,
                     __hfma2(a10[p4], W10,
                      __hfma2(a01[p4], W01, __hmul2(a11[p4], W11))));
        int z = r*NB + n;
        *reinterpret_cast<uint4*>(
            &g_featT[(z*19200 + i*160 + j)*32 + icg*8]) = outv;
    }

    // rare fallback (column-wrap): full recompute from global, f32
    while (fbmask) {
        int r = __ffs(fbmask) - 1;
        fbmask &= fbmask - 1;
        unsigned idx2 = g_idx[((r*NB + n)*hh + i)*ww + j];
        int row2 = (int)(idx2 / 640u);
        int col2 = (int)(idx2 - (unsigned)row2*640u);
        float ixv = (float)col2 * (639.f/640.f);
        float iyv = (float)row2 * (479.f/480.f);
        float x0f = floorf(ixv), y0f = floorf(iyv);
        float fwx = ixv - x0f, fwy = iyv - y0f;
        int X0 = (int)x0f, Y0 = (int)y0f;
        int xa = min(max(X0,   0), WWI-1), xb = min(max(X0+1, 0), WWI-1);
        int ya = min(max(Y0,   0), HH-1),  yb = min(max(Y0+1, 0), HH-1);
        bool okx0 = (X0 >= 0) && (X0 <= WWI-1);
        bool okx1 = (X0+1 <= WWI-1);
        bool oky0 = (Y0 >= 0) && (Y0 <= HH-1);
        bool oky1 = (Y0+1 <= HH-1);
        float w00 = (okx0 && oky0) ? (1.f-fwx)*(1.f-fwy) : 0.f;
        float w10 = (okx1 && oky0) ? fwx*(1.f-fwy) : 0.f;
        float w01 = (okx0 && oky1) ? (1.f-fwx)*fwy : 0.f;
        float w11 = (okx1 && oky1) ? fwx*fwy : 0.f;
        uint4 outv;
        __nv_bfloat16* o = reinterpret_cast<__nv_bfloat16*>(&outv);
        #pragma unroll
        for (int c = 0; c < 8; c++) {
            const float* xp = xbase + c*HWSZ;
            float v = xp[ya*WWI+xa]*w00 + xp[ya*WWI+xb]*w10
                    + xp[yb*WWI+xa]*w01 + xp[yb*WWI+xb]*w11;
            o[c] = __float2bfloat16(v);
        }
        int z = r*NB + n;
        *reinterpret_cast<uint4*>(
            &g_featT[(z*19200 + i*160 + j)*32 + icg*8]) = outv;
    }
}

// ---------------- Kernel 3: conv1 via mma.sync (bf16) + sigmoid*d -> g_adT --------
__global__ void __launch_bounds__(256) k_conv1(const float* __restrict__ ba) {
    __shared__ __align__(16) __nv_bfloat16 s_f[10*34*40];   // [row][col][ic pad40]
    __shared__ __align__(16) __nv_bfloat16 s_w[9*32*32];    // [tap][oc][ic]
    int tid = threadIdx.x, lane = tid & 31, wid = tid >> 5;
    int j0 = blockIdx.x*32, i0 = blockIdx.y*8, z = blockIdx.z;
    int n = z & 3;

    {
        const uint4* src = (const uint4*)g_wa_b;
        uint4* dst = (uint4*)s_w;
        for (int t = tid; t < 1152; t += 256) dst[t] = src[t];
    }
    for (int t = tid; t < 10*34*4; t += 256) {
        int chunk = t & 3; int lj = (t >> 2) % 34; int li = t / 136;
        int gi = i0 - 1 + li, gj = j0 - 1 + lj;
        uint4 v = make_uint4(0,0,0,0);
        if (gi >= 0 && gi < hh && gj >= 0 && gj < ww)
            v = *reinterpret_cast<const uint4*>(
                &g_featT[(z*19200 + gi*160 + gj)*32 + chunk*8]);
        *reinterpret_cast<uint4*>(&s_f[(li*34 + lj)*40 + chunk*8]) = v;
    }
    __syncthreads();

    uint32_t sfb = (uint32_t)__cvta_generic_to_shared(s_f);
    uint32_t swb = (uint32_t)__cvta_generic_to_shared(s_w);
    int r = wid;
    int m = lane & 15;
    int koff = (lane >> 4) * 8;
    uint32_t baseA0 = sfb + (uint32_t)((((r+1)*34 + (m + 1))*40 + koff) * 2);
    int lg = lane >> 3, lr = lane & 7;
    int nrow_off = ((lg & 2) ? 8 : 0) + lr;
    int kboff = (lg & 1) ? 8 : 0;

    float acc[2][4][4];
    #pragma unroll
    for (int s = 0; s < 2; s++)
        #pragma unroll
        for (int nt = 0; nt < 4; nt++)
            #pragma unroll
            for (int q = 0; q < 4; q++) acc[s][nt][q] = 0.f;

    #pragma unroll
    for (int tap = 0; tap < 9; tap++) {
        int dy = tap/3 - 1, dx = tap%3 - 1;
        int offA = (dy*34 + dx)*40*2;
        #pragma unroll
        for (int kc = 0; kc < 2; kc++) {
            uint32_t a0[4], a1[4];
            uint32_t aad = baseA0 + offA + kc*32;
            LDSM_X4(a0[0],a0[1],a0[2],a0[3], aad);
            LDSM_X4(a1[0],a1[1],a1[2],a1[3], aad + 16*40*2);
            #pragma unroll
            for (int p = 0; p < 2; p++) {
                uint32_t bad = swb + (uint32_t)((((tap*32 + p*16 + nrow_off))*32 + kc*16 + kboff) * 2);
                uint32_t b0,b1,b2,b3;
                LDSM_X4(b0,b1,b2,b3, bad);
                MMA_BF16(acc[0][2*p  ], a0[0],a0[1],a0[2],a0[3], b0,b1);
                MMA_BF16(acc[0][2*p+1], a0[0],a0[1],a0[2],a0[3], b2,b3);
                MMA_BF16(acc[1][2*p  ], a1[0],a1[1],a1[2],a1[3], b0,b1);
                MMA_BF16(acc[1][2*p+1], a1[0],a1[1],a1[2],a1[3], b2,b3);
            }
        }
    }

    int i = i0 + r;
    #pragma unroll
    for (int s = 0; s < 2; s++) {
        int cbase = s*16 + (lane >> 2);
        #pragma unroll
        for (int nt = 0; nt < 4; nt++) {
            int oc = nt*8 + 2*(lane & 3);
            float b0v = ba[oc], b1v = ba[oc+1];
            #pragma unroll
            for (int half = 0; half < 2; half++) {
                int c = cbase + half*8;
                int j = j0 + c;
                float v0 = acc[s][nt][half*2+0] + b0v;
                float v1 = acc[s][nt][half*2+1] + b1v;
                float att0 = 1.f/(1.f + __expf(-v0));
                float att1 = 1.f/(1.f + __expf(-v1));
                __nv_bfloat162 dv = *reinterpret_cast<const __nv_bfloat162*>(
                    &g_dT[(n*19200 + i*160 + j)*32 + oc]);
                __nv_bfloat162 pk;
                pk.x = __float2bfloat16(att0 * __bfloat162float(dv.x));
                pk.y = __float2bfloat16(att1 * __bfloat162float(dv.y));
                *reinterpret_cast<__nv_bfloat162*>(
                    &g_adT[(z*19200 + i*160 + j)*32 + oc]) = pk;
            }
        }
    }
}

// ---------------- Kernel 4: conv2 via mma.sync + fused loss ----------------
__global__ void __launch_bounds__(256) k_conv2(const float* __restrict__ bp) {
    __shared__ __align__(16) __nv_bfloat16 s_a[10*34*40];
    __shared__ __align__(16) __nv_bfloat16 s_w2[9*8*32];
    __shared__ float s_rg[10*36];
    __shared__ float s_red[16];
    int tid = threadIdx.x, lane = tid & 31, wid = tid >> 5;
    int j0 = blockIdx.x*32, i0 = blockIdx.y*8, z = blockIdx.z;
    int rr = z >> 2;

    {
        const uint4* src = (const uint4*)g_wp_b;
        uint4* dst = (uint4*)s_w2;
        for (int t = tid; t < 288; t += 256) dst[t] = src[t];
    }
    for (int t = tid; t < 10*34; t += 256) {
        int lcx = t % 34, lrr = t / 34;
        int gi = i0 - 1 + lrr, gj = j0 - 1 + lcx;
        float v = 0.f;
        if (gi >= 0 && gi < hh && gj >= 0 && gj < ww) v = g_rg[(z*hh + gi)*ww + gj];
        s_rg[lrr*36 + lcx] = v;
    }
    for (int t = tid; t < 10*34*4; t += 256) {
        int chunk = t & 3; int lj = (t >> 2) % 34; int li = t / 136;
        int gi = i0 - 1 + li, gj = j0 - 1 + lj;
        uint4 v = make_uint4(0,0,0,0);
        if (gi >= 0 && gi < hh && gj >= 0 && gj < ww)
            v = *reinterpret_cast<const uint4*>(
                &g_adT[(z*19200 + gi*160 + gj)*32 + chunk*8]);
        *reinterpret_cast<uint4*>(&s_a[(li*34 + lj)*40 + chunk*8]) = v;
    }
    __syncthreads();

    uint32_t sab = (uint32_t)__cvta_generic_to_shared(s_a);
    uint32_t swb = (uint32_t)__cvta_generic_to_shared(s_w2);
    int r = wid;
    int m = lane & 15;
    int koff = (lane >> 4) * 8;
    uint32_t baseA0 = sab + (uint32_t)((((r+1)*34 + (m + 1))*40 + koff) * 2);
    int nrow2 = lane & 7;
    int kboff2 = ((lane >> 3) & 1) ? 8 : 0;

    float acc[2][4];
    #pragma unroll
    for (int s = 0; s < 2; s++)
        #pragma unroll
        for (int q = 0; q < 4; q++) acc[s][q] = 0.f;

    #pragma unroll
    for (int tap = 0; tap < 9; tap++) {
        int dy = tap/3 - 1, dx = tap%3 - 1;
        int offA = (dy*34 + dx)*40*2;
        #pragma unroll
        for (int kc = 0; kc < 2; kc++) {
            uint32_t a0[4], a1[4];
            uint32_t aad = baseA0 + offA + kc*32;
            LDSM_X4(a0[0],a0[1],a0[2],a0[3], aad);
            LDSM_X4(a1[0],a1[1],a1[2],a1[3], aad + 16*40*2);
            uint32_t bad = swb + (uint32_t)(((tap*8 + nrow2)*32 + kc*16 + kboff2) * 2);
            uint32_t b0,b1;
            LDSM_X2(b0,b1, bad);
            MMA_BF16(acc[0], a0[0],a0[1],a0[2],a0[3], b0,b1);
            MMA_BF16(acc[1], a1[0],a1[1],a1[2],a1[3], b0,b1);
        }
    }

    float num = 0.f, den = 0.f;
    int ocl = 2*(lane & 3);
    if (ocl < 4) {
        #pragma unroll
        for (int s = 0; s < 2; s++) {
            #pragma unroll
            for (int q = 0; q < 4; q++) {
                int oc = ocl + (q & 1);
                int m2 = (lane >> 2) + ((q >> 1) * 8);
                int c = s*16 + m2;
                float ds = acc[s][q] + bp[oc];
                int ox = (oc >= 1) ? 1 : 0;
                int oy = (oc < 2) ? 1 : ((oc == 2) ? 0 : -1);
                float cen = s_rg[(r+1)*36 + (c+1)];
                float nbv = s_rg[(r+1+ox)*36 + (c+1+oy)];
                float grad = __logf(cen + 1e-6f) - __logf(nbv + 1e-6f);
                float a = fabsf(ds - grad);
                float sl1 = (a < 0.01f) ? (0.5f*a*a/0.01f) : (a - 0.005f);
                if (cen > 0.1f && nbv > 0.1f) { num += sl1; den += 1.f; }
            }
        }
    }
    #pragma unroll
    for (int o = 16; o > 0; o >>= 1) {
        num += __shfl_down_sync(0xffffffffu, num, o);
        den += __shfl_down_sync(0xffffffffu, den, o);
    }
    if (lane == 0) { s_red[wid] = num; s_red[8 + wid] = den; }
    __syncthreads();
    if (tid == 0) {
        float sn = 0.f, sd = 0.f;
        #pragma unroll
        for (int w = 0; w < 8; w++) { sn += s_red[w]; sd += s_red[8+w]; }
        atomicAdd(&g_num[rr], sn);
        atomicAdd(&g_den[rr], sd);
    }
}

__global__ void k_final(float* out) {
    if (threadIdx.x == 0) {
        float tot = 0.f;
        for (int r = 0; r < RR; r++) tot += g_num[r] / g_den[r];
        out[0] = tot / 20.0f;
    }
}

extern "C" void kernel_launch(void* const* d_in, const int* in_sizes, int n_in,
                              void* d_out, int out_size) {
    const float* x    = (const float*)d_in[0];
    const float* d    = (const float*)d_in[1];
    const float* gts  = (const float*)d_in[2];
    const float* rnd  = (const float*)d_in[3];
    const float* Wa   = (const float*)d_in[4];
    const float* ba   = (const float*)d_in[5];
    const float* Wp   = (const float*)d_in[6];
    const float* bp   = (const float*)d_in[7];
    float* out = (float*)d_out;

    k_zero<<<1, 32>>>();
    k_wcvt<<<36, 256>>>(Wa, Wp);
    k_dcvt<<<dim3(300, 4), 256>>>(d);

    dim3 bs1(32, 4), gs1(ww/32, hh/4, NB);
    k_pool<<<gs1, bs1>>>(gts, rnd);

    dim3 bs2(32, 4), gs2(ww/32, hh/4, NB*4);
    k_sample<<<gs2, bs2>>>(x);

    dim3 bs3(256), gs3(ww/32, hh/8, RR*NB);
    k_conv1<<<gs3, bs3>>>(ba);

    dim3 bs4(256), gs4(ww/32, hh/8, RR*NB);
    k_conv2<<<gs4, bs4>>>(bp);

    k_final<<<1, 32>>>(out);
}